// round 11
// baseline (speedup 1.0000x reference)
#include <cuda_runtime.h>
#include <cstdint>

// CTC forward loss, B=32, T=2048, V=1024, S=256. Single kernel.
// 16 CTAs x 256 threads = TWO independent batches per CTA (half h=tid>>7,
// 4 warps each) -> 2 warps/SMSP of independent dependency chains.
// Per half: halo scheme (log-space, proven R8/R9): pairs k=(token s=2k+1,
// blank s=2k+2); warp w owns pairs [64w,64w+64) (regs r=1,2) + redundant
// 32-pair halo [64w-32,64w) (reg r=0). Halos refreshed every CHUNK=8
// steps at ONE per-half named barrier (bar.sync h+1,128) that also
// publishes the next 8-row cp.async chunk. Emits prefetched 1 step ahead.

#define TT 2048
#define VV 1024
#define SS 256
#define BB 32
#define NEGF (-1e30f)
#define CHUNK 8
#define NTHREADS 256
#define NCTAS 16

__device__ float g_losses[BB];
__device__ unsigned int g_done;   // zero-init; self-resetting

__device__ __forceinline__ void cp_async16(uint32_t smem_addr, const void* gmem) {
    asm volatile("cp.async.cg.shared.global [%0], [%1], 16;\n"
                 :: "r"(smem_addr), "l"(gmem));
}
__device__ __forceinline__ void cp_commit() {
    asm volatile("cp.async.commit_group;\n" ::: "memory");
}
template <int N>
__device__ __forceinline__ void cp_wait() {
    asm volatile("cp.async.wait_group %0;\n" :: "n"(N) : "memory");
}
// Per-half barrier: named barrier id h+1, 128 threads.
__device__ __forceinline__ void half_bar(int h) {
    asm volatile("bar.sync %0, %1;" :: "r"(h + 1), "r"(128) : "memory");
}

__device__ __forceinline__ float lse2(float a, float b) {
    const float m  = fmaxf(a, b);
    const float lo = fminf(a, b);
    return m + __logf(1.0f + __expf(lo - m));
}
__device__ __forceinline__ float lse3(float x0, float x1, float x2) {
    const float lo1 = fminf(x0, x1);
    const float hi1 = fmaxf(x0, x1);
    const float m   = fmaxf(hi1, x2);
    const float o2  = fminf(hi1, x2);
    return m + __logf(1.0f + __expf(lo1 - m) + __expf(o2 - m));
}

// One DP step with emit values already in registers. w = warp within half.
__device__ __forceinline__ void ctc_step(
    const float eB, const float eT[3],
    float aT[3], float aB[3], float& a0,
    const bool rep[3], const int w, const int lane)
{
    float uT[3], uB[3];
    #pragma unroll
    for (int r = 0; r < 3; ++r) {
        uT[r] = __shfl_up_sync(0xffffffffu, aT[r], 1);
        uB[r] = __shfl_up_sync(0xffffffffu, aB[r], 1);
    }
    const float bT1 = __shfl_sync(0xffffffffu, aT[0], 31);
    const float bB1 = __shfl_sync(0xffffffffu, aB[0], 31);
    const float bT2 = __shfl_sync(0xffffffffu, aT[1], 31);
    const float bB2 = __shfl_sync(0xffffffffu, aB[1], 31);
    if (lane == 0) {
        uT[0] = NEGF; uB[0] = NEGF;   // leftmost halo pair: stale by design
        uT[1] = bT1;  uB[1] = bB1;
        uT[2] = bT2;  uB[2] = bB2;
    }

    float nB[3], nT[3];
    #pragma unroll
    for (int r = 0; r < 3; ++r) nB[r] = eB + lse2(aB[r], aT[r]);
    #pragma unroll
    for (int r = 0; r < 3; ++r)
        nT[r] = eT[r] + lse3(aT[r], uB[r], rep[r] ? uT[r] : NEGF);

    if (w == 0) {                     // reg0 of warp 0 relays a0 (ext pos 0)
        a0 += eB;
        nT[0] = NEGF;
        nB[0] = (lane == 31) ? a0 : NEGF;
    }
    #pragma unroll
    for (int r = 0; r < 3; ++r) { aT[r] = nT[r]; aB[r] = nB[r]; }
}

__global__ void __launch_bounds__(NTHREADS, 1)
ctc_fused(const float* __restrict__ lp,     // [B, T, V]
          const int* __restrict__ tok,      // [B, S]
          const int* __restrict__ tlens,    // [B]
          const int* __restrict__ slens,    // [B]
          float* __restrict__ out) {
    extern __shared__ float smem[];

    const int tid  = threadIdx.x;
    const int h    = tid >> 7;              // half (batch within CTA)
    const int lt   = tid & 127;             // local tid within half
    const int lane = lt & 31;
    const int w    = lt >> 5;               // warp within half, 0..3
    const int b    = (blockIdx.x << 1) + h;

    float* buf = smem + h * (2 * CHUNK * VV);           // [2][CHUNK][VV]
    float* bnd = smem + 2 * (2 * CHUNK * VV) + h * 512; // [2][4][32][2]

    const int Tl = tlens[b];
    const int Sl = slens[b];
    const float* lpb = lp + (size_t)b * TT * VV;

    // Labels/flags for this thread's 3 pairs: p = 64w - 32 + 32r + lane.
    int L[3]; bool rep[3];
    #pragma unroll
    for (int r = 0; r < 3; ++r) {
        const int p  = 64 * w - 32 + 32 * r + lane;
        const int pc = (p < 0) ? 0 : p;
        L[r] = tok[b * SS + pc];
        const int Lp = (p >= 1) ? tok[b * SS + p - 1] : 0;
        rep[r] = (p >= 1) && (L[r] != Lp);
    }

    // Prologue: stream rows 0..15 (chunks 0,1), one commit group per row.
    #pragma unroll 1
    for (int r0 = 0; r0 < 2 * CHUNK; ++r0) {
        const float* src = lpb + (size_t)r0 * VV + lt * 8;
        const uint32_t dst =
            (uint32_t)__cvta_generic_to_shared(buf + r0 * VV + lt * 8);
        cp_async16(dst, src);
        cp_async16(dst + 16, src + 4);
        cp_commit();
    }
    cp_wait<CHUNK>();         // rows 0..7 resident
    half_bar(h);

    // t = 0 init.
    float aT[3] = {NEGF, NEGF, NEGF};
    float aB[3] = {NEGF, NEGF, NEGF};
    float a0 = NEGF;
    if (w == 0) {
        a0 = buf[0];                          // alpha[0] = emit(0, blank)
        if (lane == 0)  aT[1] = buf[L[1]];    // alpha[1] = emit(0, tok0)
        if (lane == 31) aB[0] = a0;           // relay slot
    }

    float eB, eT[3];

    // Chunk 0: steps 1..7 (Tl >= 1024, always full). Prefetch dist 1.
    eB = buf[VV];
    eT[0] = buf[VV + L[0]]; eT[1] = buf[VV + L[1]]; eT[2] = buf[VV + L[2]];
    #pragma unroll
    for (int i = 1; i < CHUNK; ++i) {
        float neB = 0.f, neT0 = 0.f, neT1 = 0.f, neT2 = 0.f;
        if (i < CHUNK - 1) {
            const float* rp = buf + (i + 1) * VV;
            neB = rp[0]; neT0 = rp[L[0]]; neT1 = rp[L[1]]; neT2 = rp[L[2]];
        }
        ctc_step(eB, eT, aT, aB, a0, rep, w, lane);
        eB = neB; eT[0] = neT0; eT[1] = neT1; eT[2] = neT2;
    }

    // Chunks c >= 1.
    #pragma unroll 1
    for (int c = 1; c * CHUNK < Tl; ++c) {
        // Halo refresh: publish own top 32 pairs (reg2), barrier, read
        // left neighbor's. Barrier also publishes chunk c's cp.asyncs.
        const int pc = (c & 1) * 256;
        bnd[pc + w * 64 + lane * 2 + 0] = aT[2];
        bnd[pc + w * 64 + lane * 2 + 1] = aB[2];
        cp_wait<0>();
        half_bar(h);
        if (w > 0) {
            aT[0] = bnd[pc + (w - 1) * 64 + lane * 2 + 0];
            aB[0] = bnd[pc + (w - 1) * 64 + lane * 2 + 1];
        }

        const int t0 = c * CHUNK;
        float* curbuf = buf + (c & 1) * CHUNK * VV;
        float* nxtbuf = buf + ((c + 1) & 1) * CHUNK * VV;

        // Emits for step t0 (exposed once per chunk).
        eB = curbuf[0];
        eT[0] = curbuf[L[0]]; eT[1] = curbuf[L[1]]; eT[2] = curbuf[L[2]];

        #pragma unroll
        for (int i = 0; i < CHUNK; ++i) {
            const int t = t0 + i;
            const int row = t0 + CHUNK + i;   // chunk c+1, row i
            if (row < TT) {
                const float* src = lpb + (size_t)row * VV + lt * 8;
                const uint32_t dst =
                    (uint32_t)__cvta_generic_to_shared(nxtbuf + i * VV + lt * 8);
                cp_async16(dst, src);
                cp_async16(dst + 16, src + 4);
            }
            cp_commit();
            float neB = 0.f, neT0 = 0.f, neT1 = 0.f, neT2 = 0.f;
            if (i < CHUNK - 1) {
                const float* rp = curbuf + (i + 1) * VV;
                neB = rp[0]; neT0 = rp[L[0]]; neT1 = rp[L[1]]; neT2 = rp[L[2]];
            }
            if (t < Tl)                       // half-uniform guard
                ctc_step(eB, eT, aT, aB, a0, rep, w, lane);
            eB = neB; eT[0] = neT0; eT[1] = neT1; eT[2] = neT2;
        }
    }

    // Loss from pair q = Sl-1 (own pairs always exact).
    const int q = Sl - 1;
    if (w == (q >> 6) && lane == (q & 31)) {
        const bool hi = (q >> 5) & 1;
        const float fT = hi ? aT[2] : aT[1];  // alpha[2Sl-1]
        const float fB = hi ? aB[2] : aB[1];  // alpha[2Sl]
        float loss = -lse2(fB, fT);
        if (loss > 1e29f) loss = 0.0f;
        g_losses[b] = loss / (float)Sl;
        __threadfence();
    }
    __syncthreads();

    // Last-block deterministic reduction.
    if (tid == 0) {
        __threadfence();
        const unsigned v = atomicAdd(&g_done, 1u);
        if (v == NCTAS - 1) {
            __threadfence();
            float acc = 0.0f;
            #pragma unroll
            for (int i = 0; i < BB; ++i) acc += g_losses[i];
            out[0] = acc / (float)BB;
            atomicExch(&g_done, 0u);
        }
    }
}

extern "C" void kernel_launch(void* const* d_in, const int* in_sizes, int n_in,
                              void* d_out, int out_size) {
    const float* lp    = (const float*)d_in[0];  // [B,T,V] f32
    const int*   tok   = (const int*)d_in[1];    // [B,S]   i32
    const int*   tlens = (const int*)d_in[2];    // [B]     i32
    const int*   slens = (const int*)d_in[3];    // [B]     i32
    float* out = (float*)d_out;

    // 2 halves x (2 x CHUNK x VV) rows + 2 x 512 boundary floats.
    const int smem_bytes = (2 * 2 * CHUNK * VV + 1024) * (int)sizeof(float);
    cudaFuncSetAttribute(ctc_fused, cudaFuncAttributeMaxDynamicSharedMemorySize,
                         smem_bytes);
    ctc_fused<<<NCTAS, NTHREADS, smem_bytes>>>(lp, tok, tlens, slens, out);
}

// round 12
// speedup vs baseline: 1.2149x; 1.2149x over previous
#include <cuda_runtime.h>
#include <cstdint>

// CTC forward loss, B=32, T=2048, V=1024, S=256. Single kernel.
// SYSTOLIC WARPS: 32 CTAs x 256 threads (8 warps). Lane l of warp w owns
// pair p = 32w + l (ext positions s=2p+1 token aT, s=2p+2 blank aB).
// alpha_t[s] depends only on alpha_{t-1}[s'<=s], so warp w+1 may lag warp
// w. Lane 31 logs (aT,aB) each step into a 32-entry smem history ring;
// warp w+1's lane 0 reads warp w's entry (t-1). Chunk (CH=8) handshakes
// via volatile progress counters: forward (w-1 finished chunk c) and
// backpressure (w+1 finished chunk c-3, ring safety). NO __syncthreads
// in the time loop. Emits via __ldg, double-buffered one chunk ahead.
// Warp 0 lane 0 carries a0 (ext position 0, pure add).

#define TT 2048
#define VV 1024
#define SS 256
#define BB 32
#define NEGF (-1e30f)
#define CH 8
#define RING 32
#define NTHREADS 256

__device__ float g_losses[BB];
__device__ unsigned int g_done;   // zero-init; self-resetting

__device__ __forceinline__ float lse2(float a, float b) {
    const float m  = fmaxf(a, b);
    const float lo = fminf(a, b);
    return m + __logf(1.0f + __expf(lo - m));
}
__device__ __forceinline__ float lse3(float x0, float x1, float x2) {
    const float lo1 = fminf(x0, x1);
    const float hi1 = fmaxf(x0, x1);
    const float m   = fmaxf(hi1, x2);
    const float o2  = fminf(hi1, x2);
    return m + __logf(1.0f + __expf(lo1 - m) + __expf(o2 - m));
}

__global__ void __launch_bounds__(NTHREADS, 1)
ctc_fused(const float* __restrict__ lp,     // [B, T, V]
          const int* __restrict__ tok,      // [B, S]
          const int* __restrict__ tlens,    // [B]
          const int* __restrict__ slens,    // [B]
          float* __restrict__ out) {
    __shared__ float hist[8][RING][2];      // lane-31 (aT,aB) ring per warp
    __shared__ int   progress[8];           // last completed chunk per warp

    const int b    = blockIdx.x;
    const int tid  = threadIdx.x;
    const int lane = tid & 31;
    const int w    = tid >> 5;
    const int Tl   = tlens[b];
    const int Sl   = slens[b];
    const float* lpb = lp + (size_t)b * TT * VV;

    const int  p   = tid;                    // pair index 0..255
    const int  L   = tok[b * SS + p];
    const bool rep = (p > 0) && (L != tok[b * SS + p - 1]);

    if (tid < 8) progress[tid] = -1;

    // t = 0 init: alpha[0]=emit(0,blank), alpha[1]=emit(0,tok0), rest NEG.
    float aT = NEGF, aB = NEGF, a0 = NEGF;
    if (tid == 0) {
        a0 = __ldg(lpb);                     // alpha[0]
        aT = __ldg(lpb + L);                 // alpha[1] (pair 0 token)
    }
    if (lane == 31) { hist[w][0][0] = aT; hist[w][0][1] = aB; }
    __syncthreads();                          // init visibility (once)

    // Emit double buffers: chunk c (A) and c+1 (B).
    float eTa[CH], eBa[CH], eTb[CH], eBb[CH];
    #pragma unroll
    for (int i = 0; i < CH; ++i) {
        eTa[i] = __ldg(lpb + (size_t)i * VV + L);
        eBa[i] = __ldg(lpb + (size_t)i * VV);
        eTb[i] = __ldg(lpb + (size_t)(CH + i) * VV + L);
        eBb[i] = __ldg(lpb + (size_t)(CH + i) * VV);
    }

    const int nch = (Tl + CH - 1) / CH;       // chunks over t in [0, Tl)
    volatile int* vprog = progress;

    #pragma unroll 1
    for (int c = 0; c < nch; ++c) {
        // Forward wait: warp w-1 finished chunk c.
        if (w > 0)      { while (vprog[w - 1] < c) { } }
        // Backpressure: warp w+1 finished chunk c-3 (ring reuse safety).
        if (w < 7 && c >= 3) { while (vprog[w + 1] < c - 3) { } }
        __threadfence_block();                // acquire hist entries

        const bool useA = ((c & 1) == 0);

        // Compute CH steps of chunk c.
        #pragma unroll
        for (int i = 0; i < CH; ++i) {
            const int t = c * CH + i;
            if (t >= 1 && t < Tl) {           // warp-uniform
                const float eT = useA ? eTa[i] : eTb[i];
                const float eB = useA ? eBa[i] : eBb[i];
                float uT = __shfl_up_sync(0xffffffffu, aT, 1);
                float uB = __shfl_up_sync(0xffffffffu, aB, 1);
                if (lane == 0) {
                    if (w == 0) { uT = NEGF; uB = a0; }
                    else {
                        uT = hist[w - 1][(t - 1) & (RING - 1)][0];
                        uB = hist[w - 1][(t - 1) & (RING - 1)][1];
                    }
                }
                const float nT = eT + lse3(aT, uB, rep ? uT : NEGF);
                const float nB = eB + lse2(aB, aT);
                if (tid == 0) a0 += eB;       // after uB consumed old a0
                aT = nT; aB = nB;
                if (lane == 31) {
                    hist[w][t & (RING - 1)][0] = aT;
                    hist[w][t & (RING - 1)][1] = aB;
                }
            }
        }

        __threadfence_block();                // release hist writes
        if (lane == 0) vprog[w] = c;          // publish

        // Prefetch emits for chunk c+2 into the buffer just consumed.
        {
            const int base = (c + 2) * CH;
            #pragma unroll
            for (int i = 0; i < CH; ++i) {
                int tq = base + i; if (tq > TT - 1) tq = TT - 1;
                const float vT = __ldg(lpb + (size_t)tq * VV + L);
                const float vB = __ldg(lpb + (size_t)tq * VV);
                if (useA) { eTa[i] = vT; eBa[i] = vB; }
                else      { eTb[i] = vT; eBb[i] = vB; }
            }
        }
    }

    // Loss: pair q = Sl-1 holds alpha[2Sl-1]=aT, alpha[2Sl]=aB.
    if (tid == Sl - 1) {
        float loss = -lse2(aB, aT);
        if (loss > 1e29f) loss = 0.0f;
        g_losses[b] = loss / (float)Sl;
        __threadfence();
    }
    __syncthreads();

    // Last-block deterministic reduction.
    if (tid == 0) {
        __threadfence();
        const unsigned v = atomicAdd(&g_done, 1u);
        if (v == BB - 1) {
            __threadfence();
            float acc = 0.0f;
            #pragma unroll
            for (int i = 0; i < BB; ++i) acc += g_losses[i];
            out[0] = acc / (float)BB;
            atomicExch(&g_done, 0u);
        }
    }
}

extern "C" void kernel_launch(void* const* d_in, const int* in_sizes, int n_in,
                              void* d_out, int out_size) {
    const float* lp    = (const float*)d_in[0];  // [B,T,V] f32
    const int*   tok   = (const int*)d_in[1];    // [B,S]   i32
    const int*   tlens = (const int*)d_in[2];    // [B]     i32
    const int*   slens = (const int*)d_in[3];    // [B]     i32
    float* out = (float*)d_out;

    ctc_fused<<<BB, NTHREADS>>>(lp, tok, tlens, slens, out);
}

// round 13
// speedup vs baseline: 1.3935x; 1.1470x over previous
#include <cuda_runtime.h>
#include <cstdint>

// CTC forward loss, B=32, T=2048, V=1024, S=256. Single kernel.
// 16 CTAs x 512 threads = TWO fully independent batches per CTA
// (half h = tid>>8, 8 warps each). Per half: R5 layout — thread lt owns
// pair lt (ext s=2lt+1 token aT, s=2lt+2 blank aB); lt 0 also carries
// ext pos 0 (a0). Neighbors via shfl_up; warp boundaries via smem bnd
// (parity double-buffered). Each half steps t=1..Tl-1 with its OWN
// named barrier (bar.sync h+1, 256) and own 8-stage cp.async pipeline.
// LSE computed in log2 domain (raw ex2/lg2, no hidden FFMA on chain);
// emits scaled by log2(e) at prefetch (off-chain).

#define TT 2048
#define VV 1024
#define SS 256
#define BB 32
#define NEGF (-1e30f)
#define STAGES 8
#define NTHREADS 512
#define NCTAS 16
#define LOG2E 1.4426950408889634f
#define LN2   0.6931471805599453f

__device__ float g_losses[BB];
__device__ unsigned int g_done;   // zero-init; self-resetting

__device__ __forceinline__ void cp_async16(uint32_t smem_addr, const void* gmem) {
    asm volatile("cp.async.cg.shared.global [%0], [%1], 16;\n"
                 :: "r"(smem_addr), "l"(gmem));
}
__device__ __forceinline__ void cp_commit() {
    asm volatile("cp.async.commit_group;\n" ::: "memory");
}
template <int N>
__device__ __forceinline__ void cp_wait() {
    asm volatile("cp.async.wait_group %0;\n" :: "n"(N) : "memory");
}
__device__ __forceinline__ void half_bar(int h) {
    asm volatile("bar.sync %0, %1;" :: "r"(h + 1), "r"(256) : "memory");
}
__device__ __forceinline__ float ex2(float x) {
    float y; asm("ex2.approx.ftz.f32 %0, %1;" : "=f"(y) : "f"(x)); return y;
}
__device__ __forceinline__ float lg2(float x) {
    float y; asm("lg2.approx.ftz.f32 %0, %1;" : "=f"(y) : "f"(x)); return y;
}

// log2-domain LSE: m + log2(1 + 2^(lo-m)).
__device__ __forceinline__ float lse2_2(float a, float b) {
    const float m  = fmaxf(a, b);
    const float lo = fminf(a, b);
    return m + lg2(1.0f + ex2(lo - m));
}
__device__ __forceinline__ float lse3_2(float x0, float x1, float x2) {
    const float lo1 = fminf(x0, x1);
    const float hi1 = fmaxf(x0, x1);
    const float m   = fmaxf(hi1, x2);
    const float o2  = fminf(hi1, x2);
    return m + lg2(1.0f + ex2(lo1 - m) + ex2(o2 - m));
}

__global__ void __launch_bounds__(NTHREADS, 1)
ctc_fused(const float* __restrict__ lp,     // [B, T, V]
          const int* __restrict__ tok,      // [B, S]
          const int* __restrict__ tlens,    // [B]
          const int* __restrict__ slens,    // [B]
          float* __restrict__ out) {
    extern __shared__ float smem[];

    const int tid  = threadIdx.x;
    const int h    = tid >> 8;              // half (batch within CTA)
    const int lt   = tid & 255;             // local tid within half
    const int lane = tid & 31;
    const int wh   = lt >> 5;               // warp within half, 0..7
    const int b    = (blockIdx.x << 1) + h;

    float* rows = smem + h * (STAGES * VV);            // [STAGES][VV]
    float* bnd  = smem + 2 * (STAGES * VV) + h * 32;   // [parity][8][2]

    const int Tl = tlens[b];
    const int Sl = slens[b];
    const float* lpb = lp + (size_t)b * TT * VV;

    const int  L   = tok[b * SS + lt];
    const bool rep = (lt > 0) && (L != tok[b * SS + lt - 1]);

    // Prologue: rows 0..7, one commit group per row (256 thr x 16B = 4KB).
    #pragma unroll
    for (int st = 0; st < STAGES; ++st) {
        cp_async16((uint32_t)__cvta_generic_to_shared(rows + st * VV + lt * 4),
                   lpb + (size_t)st * VV + lt * 4);
        cp_commit();
    }
    cp_wait<5>();            // rows 0..2 resident
    __syncthreads();         // one block-wide sync: smem carve + init

    // t = 0 init (log2 domain).
    float aT = (lt == 0) ? rows[L] * LOG2E : NEGF;
    float aB = NEGF;
    float a0 = rows[0] * LOG2E;              // thread lt==0 only

    // Emit regs (log2 domain): (eT,eB) row t, (eTn,eBn) row t+1.
    float eT  = rows[VV + L]     * LOG2E, eB  = rows[VV]     * LOG2E;
    float eTn = rows[2 * VV + L] * LOG2E, eBn = rows[2 * VV] * LOG2E;

    if (lane == 31) { bnd[wh * 2 + 0] = aT; bnd[wh * 2 + 1] = aB; } // parity 0
    half_bar(h);

    #pragma unroll 1
    for (int t = 1; t < Tl; ++t) {
        const int pa = (t - 1) & 1;
        const int pb = t & 1;

        float pT = __shfl_up_sync(0xffffffffu, aT, 1);
        float pB = __shfl_up_sync(0xffffffffu, aB, 1);
        if (lane == 0) {
            if (wh) { pT = bnd[pa * 16 + (wh - 1) * 2 + 0];
                      pB = bnd[pa * 16 + (wh - 1) * 2 + 1]; }
            else    { pT = NEGF; pB = a0; }
        }
        const float nT = eT + lse3_2(aT, pB, rep ? pT : NEGF);
        const float nB = eB + lse2_2(aB, aT);
        if (lt == 0) a0 = eB + a0;
        aT = nT; aB = nB;
        if (lane == 31) { bnd[pb * 16 + wh * 2 + 0] = aT;
                          bnd[pb * 16 + wh * 2 + 1] = aB; }

        // Rotate emits; prefetch row t+2 (resident via wait<5>).
        eT = eTn; eB = eBn;
        const int sE = (t + 2) & (STAGES - 1);
        eTn = rows[sE * VV + L] * LOG2E;
        eBn = rows[sE * VV]     * LOG2E;

        // Stream row t+7 (skip past own end; commit group always).
        {
            const int rW = t + STAGES - 1;
            if (rW < Tl) {
                const int sW = rW & (STAGES - 1);
                cp_async16((uint32_t)__cvta_generic_to_shared(rows + sW * VV + lt * 4),
                           lpb + (size_t)rW * VV + lt * 4);
            }
        }
        cp_commit();
        cp_wait<5>();
        half_bar(h);         // publishes bnd[pb] + cp.async landings
    }

    // Loss: thread lt = Sl-1 holds alpha[2Sl-1]=aT, alpha[2Sl]=aB (log2).
    if (lt == Sl - 1) {
        float loss = -lse2_2(aB, aT) * LN2;
        if (!(loss <= 1e29f)) loss = 0.0f;   // guard inf/NaN too
        g_losses[b] = loss / (float)Sl;
        __threadfence();
    }
    __syncthreads();

    // Last-block deterministic reduction (fixed order).
    if (tid == 0) {
        __threadfence();
        const unsigned v = atomicAdd(&g_done, 1u);
        if (v == NCTAS - 1) {
            __threadfence();
            float acc = 0.0f;
            #pragma unroll
            for (int i = 0; i < BB; ++i) acc += g_losses[i];
            out[0] = acc / (float)BB;
            atomicExch(&g_done, 0u);
        }
    }
}

extern "C" void kernel_launch(void* const* d_in, const int* in_sizes, int n_in,
                              void* d_out, int out_size) {
    const float* lp    = (const float*)d_in[0];  // [B,T,V] f32
    const int*   tok   = (const int*)d_in[1];    // [B,S]   i32
    const int*   tlens = (const int*)d_in[2];    // [B]     i32
    const int*   slens = (const int*)d_in[3];    // [B]     i32
    float* out = (float*)d_out;

    // 2 halves x STAGES x 4KB rows + 2 x 32 boundary floats.
    const int smem_bytes = (2 * STAGES * VV + 64) * (int)sizeof(float);
    cudaFuncSetAttribute(ctc_fused, cudaFuncAttributeMaxDynamicSharedMemorySize,
                         smem_bytes);
    ctc_fused<<<NCTAS, NTHREADS, smem_bytes>>>(lp, tok, tlens, slens, out);
}

// round 14
// speedup vs baseline: 1.6307x; 1.1702x over previous
#include <cuda_runtime.h>
#include <cstdint>

// CTC forward loss, B=32, T=2048, V=1024, S=256. Single kernel.
// 32 CTAs x 256 threads (8 warps), one batch per CTA, R5 structure:
// thread p owns pair p (ext s=2p+1 token aT, s=2p+2 blank aB); thread 0
// also ext pos 0 (a0). Per-step __syncthreads; 8-stage cp.async rows.
// THIS ROUND: LINEAR-DOMAIN alpha with PER-THREAD binary exponent K
// (stored * 2^K = true), renormalized every step by an exact power of 2.
// Neighbor inflow rescaled by 2^(Ku-K) built with integer ops; frontier
// threads adopt neighbor K. No MUFU on the dependency chain (emits are
// ex2'd at prefetch, off-chain). R10's failure (one scale per warp,
// 2^126 spread across 64 pairs) is fixed: one scale per PAIR, and
// adjacent-pair ratios are bounded (~2^25) by the per-step re-feeding.

#define TT 2048
#define VV 1024
#define SS 256
#define BB 32
#define STAGES 8
#define NTHREADS 256
#define LOG2E 1.4426950408889634f
#define LN2   0.6931471805599453f

__device__ float g_losses[BB];
__device__ unsigned int g_done;   // zero-init; self-resetting

__device__ __forceinline__ void cp_async16(uint32_t smem_addr, const void* gmem) {
    asm volatile("cp.async.cg.shared.global [%0], [%1], 16;\n"
                 :: "r"(smem_addr), "l"(gmem));
}
__device__ __forceinline__ void cp_commit() {
    asm volatile("cp.async.commit_group;\n" ::: "memory");
}
template <int N>
__device__ __forceinline__ void cp_wait() {
    asm volatile("cp.async.wait_group %0;\n" :: "n"(N) : "memory");
}
__device__ __forceinline__ float ex2(float x) {
    float y; asm("ex2.approx.ftz.f32 %0, %1;" : "=f"(y) : "f"(x)); return y;
}

__global__ void __launch_bounds__(NTHREADS, 1)
ctc_fused(const float* __restrict__ lp,     // [B, T, V]
          const int* __restrict__ tok,      // [B, S]
          const int* __restrict__ tlens,    // [B]
          const int* __restrict__ slens,    // [B]
          float* __restrict__ out) {
    __shared__ float rows[STAGES][VV];      // 32 KB streamed log-prob rows
    __shared__ float bndT[2][8], bndB[2][8];
    __shared__ int   bndK[2][8];

    const int b    = blockIdx.x;
    const int tid  = threadIdx.x;
    const int lane = tid & 31;
    const int w    = tid >> 5;
    const int Tl   = tlens[b];
    const int Sl   = slens[b];
    const float* lpb = lp + (size_t)b * TT * VV;

    const int   L    = tok[b * SS + tid];
    const float repf = ((tid > 0) && (L != tok[b * SS + tid - 1])) ? 1.0f : 0.0f;

    // Prologue: stream rows 0..7 (256 thr x 16B = 4KB/row).
    #pragma unroll
    for (int st = 0; st < STAGES; ++st) {
        cp_async16((uint32_t)__cvta_generic_to_shared(&rows[st][tid * 4]),
                   lpb + (size_t)st * VV + tid * 4);
        cp_commit();
    }
    cp_wait<5>();            // rows 0..2 resident
    __syncthreads();

    // t = 0 init (linear; stored * 2^K = true, K = 0).
    float aT = 0.0f, aB = 0.0f, a0 = 0.0f;
    int   K  = 0;
    if (tid == 0) {
        a0 = ex2(rows[0][0] * LOG2E);        // alpha[0] = p0(blank)
        aT = ex2(rows[0][L] * LOG2E);        // alpha[1] = p0(tok0)
    }

    // Emit regs (linear probs): (eT,eB) for t, (eTn,eBn) for t+1.
    float eT  = ex2(rows[1][L] * LOG2E), eB  = ex2(rows[1][0] * LOG2E);
    float eTn = ex2(rows[2][L] * LOG2E), eBn = ex2(rows[2][0] * LOG2E);

    if (lane == 31) { bndT[0][w] = aT; bndB[0][w] = aB; bndK[0][w] = K; }
    __syncthreads();

    #pragma unroll 1
    for (int t = 1; t < Tl; ++t) {
        const int pa = (t - 1) & 1;
        const int pb = t & 1;

        // Neighbor pair (p-1) state at t-1.
        float uT = __shfl_up_sync(0xffffffffu, aT, 1);
        float uB = __shfl_up_sync(0xffffffffu, aB, 1);
        int   Ku = __shfl_up_sync(0xffffffffu, K, 1);
        if (lane == 0) {
            if (w) { uT = bndT[pa][w - 1]; uB = bndB[pa][w - 1]; Ku = bndK[pa][w - 1]; }
            else   { uT = 0.0f; uB = a0; Ku = K; }   // a0 shares thread-0's K
        }

        // Scale for neighbor inflow: s1 = 2^(Ku - K'), adopt K' on frontier.
        const bool nz = (uB == 0.0f) && (uT == 0.0f);   // neighbor empty
        const bool pz = (aT == 0.0f) && (aB == 0.0f);   // own empty
        const int  Ke = pz ? Ku : K;
        int d = Ku - Ke;
        d = (d > 126) ? 126 : d;
        const float s1 = (nz || d < -126)
                         ? 0.0f : __int_as_float((127 + d) << 23);
        K = Ke;

        // Linear DP step (no MUFU).
        const float tin = fmaf(repf, uT, uB);       // uB + rep*uT
        const float inT = fmaf(tin, s1, aT);
        float nT = eT * inT;
        float nB = eB * (aB + aT);
        const float na0 = eB * a0;                  // meaningful on tid 0

        // Per-thread renorm by exact power of 2: max -> [0.5, 1).
        float mx = fmaxf(nT, nB);
        if (tid == 0) mx = fmaxf(mx, na0);
        const int be = (__float_as_int(mx) >> 23) & 255;
        const bool z = (be == 0);
        K += z ? 0 : (be - 126);
        const float sc = z ? 1.0f : __int_as_float((253 - be) << 23);
        aT = nT * sc;
        aB = nB * sc;
        a0 = na0 * sc;

        if (lane == 31) { bndT[pb][w] = aT; bndB[pb][w] = aB; bndK[pb][w] = K; }

        // Rotate emits; prefetch row t+2 (resident via wait<5>), ex2 off-chain.
        eT = eTn; eB = eBn;
        const int sE = (t + 2) & (STAGES - 1);
        eTn = ex2(rows[sE][L] * LOG2E);
        eBn = ex2(rows[sE][0] * LOG2E);

        // Stream row t+7 (skip past end; commit group always).
        {
            const int rW = t + STAGES - 1;
            if (rW < Tl) {
                const int sW = rW & (STAGES - 1);
                cp_async16((uint32_t)__cvta_generic_to_shared(&rows[sW][tid * 4]),
                           lpb + (size_t)rW * VV + tid * 4);
            }
        }
        cp_commit();
        cp_wait<5>();
        __syncthreads();
    }

    // Loss: thread Sl-1 holds alpha[2Sl-1]=aT, alpha[2Sl]=aB (x 2^K).
    if (tid == Sl - 1) {
        const float s = aT + aB;
        float loss = -((float)K * LN2 + __logf(s));
        if (!(loss <= 1e29f)) loss = 0.0f;   // s==0 -> inf -> 0 (reference)
        g_losses[b] = loss / (float)Sl;
        __threadfence();
    }
    __syncthreads();

    // Last-block deterministic reduction (fixed order).
    if (tid == 0) {
        __threadfence();
        const unsigned v = atomicAdd(&g_done, 1u);
        if (v == BB - 1) {
            __threadfence();
            float acc = 0.0f;
            #pragma unroll
            for (int i = 0; i < BB; ++i) acc += g_losses[i];
            out[0] = acc / (float)BB;
            atomicExch(&g_done, 0u);
        }
    }
}

extern "C" void kernel_launch(void* const* d_in, const int* in_sizes, int n_in,
                              void* d_out, int out_size) {
    const float* lp    = (const float*)d_in[0];  // [B,T,V] f32
    const int*   tok   = (const int*)d_in[1];    // [B,S]   i32
    const int*   tlens = (const int*)d_in[2];    // [B]     i32
    const int*   slens = (const int*)d_in[3];    // [B]     i32
    float* out = (float*)d_out;

    ctc_fused<<<BB, NTHREADS>>>(lp, tok, tlens, slens, out);
}